// round 14
// baseline (speedup 1.0000x reference)
#include <cuda_runtime.h>
#include <cuda_bf16.h>
#include <cstdint>

// CRF NLL via bf16 HMMA recurrence. sm_100a.
// alpha: 16 seqs x 64 tags bf16; per step D = A @ E (m16n8k16 mma), then
// D * exp(em) / row-scale -> repack (lane-local!) -> smem -> next A.
#define B_ 256
#define S_ 1024
#define T_ 64
#define SEQ 16      // seqs per block = mma M
#define PFD 4       // emission prefetch ring depth

__device__ float g_diff[B_];

__device__ __forceinline__ float bflo(uint32_t w) { return __uint_as_float(w << 16); }
__device__ __forceinline__ float bfhi(uint32_t w) { return __uint_as_float(w & 0xffff0000u); }
__device__ __forceinline__ uint32_t bfpack(float lo, float hi) {
    uint32_t r;
    asm("cvt.rn.bf16x2.f32 %0, %1, %2;" : "=r"(r) : "f"(hi), "f"(lo));
    return r;
}
__device__ __forceinline__ void mma16816(float& d0, float& d1, float& d2, float& d3,
                                         uint32_t a0, uint32_t a1, uint32_t a2, uint32_t a3,
                                         uint32_t b0, uint32_t b1) {
    asm volatile(
        "mma.sync.aligned.m16n8k16.row.col.f32.bf16.bf16.f32 "
        "{%0,%1,%2,%3}, {%4,%5,%6,%7}, {%8,%9}, {%0,%1,%2,%3};"
        : "+f"(d0), "+f"(d1), "+f"(d2), "+f"(d3)
        : "r"(a0), "r"(a1), "r"(a2), "r"(a3), "r"(b0), "r"(b1));
}

// 16 blocks x 128 threads. Warp w covers output cols [16w, 16w+16) (2 n-tiles)
// and supplies k-tile w of next A. Region layout: usm[buf][lane][20 words];
// region(l) holds lane l's A fragment for all 4 k-tiles (4 x 16B, 80B stride).
__global__ void __launch_bounds__(128) crf_hmma_kernel(
    const float* __restrict__ emissions,   // (B, S, T) f32
    const int* __restrict__ tags,          // (B, S) int32
    const float* __restrict__ trans,       // (T, T) f32
    const float* __restrict__ startT,      // (T,)
    const float* __restrict__ endT)        // (T,)
{
    const int tid = threadIdx.x;
    const int w   = tid >> 5;
    const int l   = tid & 31;
    const int r0  = l >> 2;     // row group (seq r0 and r0+8)
    const int cq  = l & 3;      // quad col
    const int b0  = blockIdx.x * SEQ;
    const int c0  = w * 16 + 2 * cq;   // this thread's first col (pairs c0,c0+1 and +8,+9)

    __shared__ __align__(16) uint32_t usm[2][32][20];  // 2 x 32 regions x 80B
    __shared__ double psm[SEQ];

    // ── B fragments: E = exp(trans), col-major k16n8 fragments, constant. ──
    // bfr[kt][nt][0]: halves (k0, j), (k0+1, j); [1]: (k0+8, j), (k0+9, j)
    // with k0 = kt*16 + 2*cq, j = w*16 + nt*8 + r0.
    uint32_t bfr[4][2][2];
#pragma unroll
    for (int kt = 0; kt < 4; ++kt)
#pragma unroll
        for (int nt = 0; nt < 2; ++nt) {
            int k0 = kt * 16 + 2 * cq;
            int j  = w * 16 + nt * 8 + r0;
            bfr[kt][nt][0] = bfpack(__expf(__ldg(trans + (k0 + 0) * T_ + j)),
                                    __expf(__ldg(trans + (k0 + 1) * T_ + j)));
            bfr[kt][nt][1] = bfpack(__expf(__ldg(trans + (k0 + 8) * T_ + j)),
                                    __expf(__ldg(trans + (k0 + 9) * T_ + j)));
        }

    const float* emA = emissions + (size_t)(b0 + r0) * S_ * T_;      // row r0
    const float* emB = emissions + (size_t)(b0 + r0 + 8) * S_ * T_;  // row r0+8

    // ── t = 0 init: u0[r][c] = exp(start[c] + em[r][0][c]) ──
    {
        float sA0 = __ldg(startT + c0),     sA1 = __ldg(startT + c0 + 1);
        float sB0 = __ldg(startT + c0 + 8), sB1 = __ldg(startT + c0 + 9);
        uint32_t p0 = bfpack(__expf(sA0 + __ldg(emA + c0)),     __expf(sA1 + __ldg(emA + c0 + 1)));
        uint32_t p1 = bfpack(__expf(sA0 + __ldg(emB + c0)),     __expf(sA1 + __ldg(emB + c0 + 1)));
        uint32_t p2 = bfpack(__expf(sB0 + __ldg(emA + c0 + 8)), __expf(sB1 + __ldg(emA + c0 + 9)));
        uint32_t p3 = bfpack(__expf(sB0 + __ldg(emB + c0 + 8)), __expf(sB1 + __ldg(emB + c0 + 9)));
        uint4* dst = (uint4*)&usm[0][l][w * 4];
        *dst = make_uint4(p0, p1, p2, p3);
    }

    // Emission prefetch ring: er[slot][4 pairs] for rows rA,rB cols c0,c0+8.
    float2 er[PFD][4];
#pragma unroll
    for (int k = 0; k < PFD; ++k) {
        int t = 1 + k;
        er[k][0] = __ldg((const float2*)(emA + (size_t)t * T_ + c0));
        er[k][1] = __ldg((const float2*)(emB + (size_t)t * T_ + c0));
        er[k][2] = __ldg((const float2*)(emA + (size_t)t * T_ + c0 + 8));
        er[k][3] = __ldg((const float2*)(emB + (size_t)t * T_ + c0 + 8));
    }

    double cAd = 0.0, cBd = 0.0;   // log-scale for rows r0, r0+8 (warp 0 tracks)
    __syncthreads();

    int cur = 0;

    // ── Main loop: t = 1..1016 (254 chunks of 4), tail 7 steps. ──
    int t = 1;
#pragma unroll 1
    for (int tb = 0; tb < 254; ++tb) {
#pragma unroll
        for (int k = 0; k < 4; ++k, ++t) {
            // Per-row scale = u_prev[row][tag0] (region 4*r0, words 0,1).
            uint2 sw = *(const uint2*)&usm[cur][4 * r0][0];
            float s0 = bflo(sw.x), s1 = bflo(sw.y);
            float rs0 = __frcp_rn(s0), rs1 = __frcp_rn(s1);
            if (w == 0) { cAd += (double)__logf(s0); cBd += (double)__logf(s1); }

            // A fragments: 4 k-tiles from own region.
            const uint4* ap = (const uint4*)&usm[cur][l][0];
            uint4 af0 = ap[0], af1 = ap[1], af2 = ap[2], af3 = ap[3];

            float d0 = 0.f, d1 = 0.f, d2 = 0.f, d3 = 0.f;   // n-tile 0
            float e0 = 0.f, e1 = 0.f, e2 = 0.f, e3 = 0.f;   // n-tile 1
            mma16816(d0, d1, d2, d3, af0.x, af0.y, af0.z, af0.w, bfr[0][0][0], bfr[0][0][1]);
            mma16816(e0, e1, e2, e3, af0.x, af0.y, af0.z, af0.w, bfr[0][1][0], bfr[0][1][1]);
            mma16816(d0, d1, d2, d3, af1.x, af1.y, af1.z, af1.w, bfr[1][0][0], bfr[1][0][1]);
            mma16816(e0, e1, e2, e3, af1.x, af1.y, af1.z, af1.w, bfr[1][1][0], bfr[1][1][1]);
            mma16816(d0, d1, d2, d3, af2.x, af2.y, af2.z, af2.w, bfr[2][0][0], bfr[2][0][1]);
            mma16816(e0, e1, e2, e3, af2.x, af2.y, af2.z, af2.w, bfr[2][1][0], bfr[2][1][1]);
            mma16816(d0, d1, d2, d3, af3.x, af3.y, af3.z, af3.w, bfr[3][0][0], bfr[3][0][1]);
            mma16816(e0, e1, e2, e3, af3.x, af3.y, af3.z, af3.w, bfr[3][1][0], bfr[3][1][1]);

            // Emission factors (hidden behind the mma chain).
            float2 mA0 = er[k][0], mB0 = er[k][1], mA8 = er[k][2], mB8 = er[k][3];
            float fA0 = __expf(mA0.x) * rs0, fA1 = __expf(mA0.y) * rs0;
            float fB0 = __expf(mB0.x) * rs1, fB1 = __expf(mB0.y) * rs1;
            float fA8 = __expf(mA8.x) * rs0, fA9 = __expf(mA8.y) * rs0;
            float fB8 = __expf(mB8.x) * rs1, fB9 = __expf(mB8.y) * rs1;

            // Prefetch t+PFD (always < 1024 here since t <= 1016).
            {
                int tp = t + PFD;
                er[k][0] = __ldg((const float2*)(emA + (size_t)tp * T_ + c0));
                er[k][1] = __ldg((const float2*)(emB + (size_t)tp * T_ + c0));
                er[k][2] = __ldg((const float2*)(emA + (size_t)tp * T_ + c0 + 8));
                er[k][3] = __ldg((const float2*)(emB + (size_t)tp * T_ + c0 + 8));
            }

            // Scale, pack (lane-local D->A), store k-tile w of next A.
            uint32_t p0 = bfpack(d0 * fA0, d1 * fA1);
            uint32_t p1 = bfpack(d2 * fB0, d3 * fB1);
            uint32_t p2 = bfpack(e0 * fA8, e1 * fA9);
            uint32_t p3 = bfpack(e2 * fB8, e3 * fB9);
            *(uint4*)&usm[cur ^ 1][l][w * 4] = make_uint4(p0, p1, p2, p3);

            cur ^= 1;
            __syncthreads();
        }
    }
    // Tail: t = 1017..1023, fully unrolled (compile-time prefetch guards).
#pragma unroll
    for (int kk = 0; kk < 7; ++kk) {
        const int tt = 1017 + kk;
        const int slot = (tt - 1) & 3;

        uint2 sw = *(const uint2*)&usm[cur][4 * r0][0];
        float s0 = bflo(sw.x), s1 = bflo(sw.y);
        float rs0 = __frcp_rn(s0), rs1 = __frcp_rn(s1);
        if (w == 0) { cAd += (double)__logf(s0); cBd += (double)__logf(s1); }

        const uint4* ap = (const uint4*)&usm[cur][l][0];
        uint4 af0 = ap[0], af1 = ap[1], af2 = ap[2], af3 = ap[3];

        float d0 = 0.f, d1 = 0.f, d2 = 0.f, d3 = 0.f;
        float e0 = 0.f, e1 = 0.f, e2 = 0.f, e3 = 0.f;
        mma16816(d0, d1, d2, d3, af0.x, af0.y, af0.z, af0.w, bfr[0][0][0], bfr[0][0][1]);
        mma16816(e0, e1, e2, e3, af0.x, af0.y, af0.z, af0.w, bfr[0][1][0], bfr[0][1][1]);
        mma16816(d0, d1, d2, d3, af1.x, af1.y, af1.z, af1.w, bfr[1][0][0], bfr[1][0][1]);
        mma16816(e0, e1, e2, e3, af1.x, af1.y, af1.z, af1.w, bfr[1][1][0], bfr[1][1][1]);
        mma16816(d0, d1, d2, d3, af2.x, af2.y, af2.z, af2.w, bfr[2][0][0], bfr[2][0][1]);
        mma16816(e0, e1, e2, e3, af2.x, af2.y, af2.z, af2.w, bfr[2][1][0], bfr[2][1][1]);
        mma16816(d0, d1, d2, d3, af3.x, af3.y, af3.z, af3.w, bfr[3][0][0], bfr[3][0][1]);
        mma16816(e0, e1, e2, e3, af3.x, af3.y, af3.z, af3.w, bfr[3][1][0], bfr[3][1][1]);

        float2 mA0 = er[slot][0], mB0 = er[slot][1], mA8 = er[slot][2], mB8 = er[slot][3];
        float fA0 = __expf(mA0.x) * rs0, fA1 = __expf(mA0.y) * rs0;
        float fB0 = __expf(mB0.x) * rs1, fB1 = __expf(mB0.y) * rs1;
        float fA8 = __expf(mA8.x) * rs0, fA9 = __expf(mA8.y) * rs0;
        float fB8 = __expf(mB8.x) * rs1, fB9 = __expf(mB8.y) * rs1;

        if (tt + PFD < S_) {
            int tp = tt + PFD;
            er[slot][0] = __ldg((const float2*)(emA + (size_t)tp * T_ + c0));
            er[slot][1] = __ldg((const float2*)(emB + (size_t)tp * T_ + c0));
            er[slot][2] = __ldg((const float2*)(emA + (size_t)tp * T_ + c0 + 8));
            er[slot][3] = __ldg((const float2*)(emB + (size_t)tp * T_ + c0 + 8));
        }

        uint32_t p0 = bfpack(d0 * fA0, d1 * fA1);
        uint32_t p1 = bfpack(d2 * fB0, d3 * fB1);
        uint32_t p2 = bfpack(e0 * fA8, e1 * fA9);
        uint32_t p3 = bfpack(e2 * fB8, e3 * fB9);
        *(uint4*)&usm[cur ^ 1][l][w * 4] = make_uint4(p0, p1, p2, p3);

        cur ^= 1;
        __syncthreads();
    }

    // ── partition_r = c_r + log(sum_j u_final[r][j] * exp(end_j)) ──
    // Regions are identical for all warps' reads; warp 0 reduces.
    if (w == 0) {
        float pA = 0.f, pB = 0.f;
        const uint4* ap = (const uint4*)&usm[cur][l][0];
#pragma unroll
        for (int kt = 0; kt < 4; ++kt) {
            uint4 a = ap[kt];
            int cc = kt * 16 + 2 * cq;
            float w0 = __expf(__ldg(endT + cc)),     w1 = __expf(__ldg(endT + cc + 1));
            float w8 = __expf(__ldg(endT + cc + 8)), w9 = __expf(__ldg(endT + cc + 9));
            pA += bflo(a.x) * w0 + bfhi(a.x) * w1 + bflo(a.z) * w8 + bfhi(a.z) * w9;
            pB += bflo(a.y) * w0 + bfhi(a.y) * w1 + bflo(a.w) * w8 + bfhi(a.w) * w9;
        }
        pA += __shfl_xor_sync(0xffffffffu, pA, 1);
        pA += __shfl_xor_sync(0xffffffffu, pA, 2);
        pB += __shfl_xor_sync(0xffffffffu, pB, 1);
        pB += __shfl_xor_sync(0xffffffffu, pB, 2);
        if (cq == 0) {
            psm[r0]     = cAd + (double)__logf(pA);
            psm[r0 + 8] = cBd + (double)__logf(pB);
        }
    }
    __syncthreads();

    // ── Gold-path score: 8 threads per sequence. ──
    {
        int seq = tid >> 3;
        int ln  = tid & 7;
        const int* tg = tags + (size_t)(b0 + seq) * S_;
        const float* emS = emissions + (size_t)(b0 + seq) * S_ * T_;
        float sc = 0.f;
        for (int tt = ln; tt < S_; tt += 8) {
            int t0 = tg[tt];
            sc += __ldg(emS + (size_t)tt * T_ + t0);
            if (tt + 1 < S_) sc += __ldg(trans + t0 * T_ + tg[tt + 1]);
        }
        sc += __shfl_xor_sync(0xffffffffu, sc, 1);
        sc += __shfl_xor_sync(0xffffffffu, sc, 2);
        sc += __shfl_xor_sync(0xffffffffu, sc, 4);
        if (ln == 0) {
            sc += __ldg(startT + tg[0]) + __ldg(endT + tg[S_ - 1]);
            g_diff[b0 + seq] = (float)(psm[seq] - (double)sc);
        }
    }
}

__global__ void crf_reduce_kernel(float* __restrict__ out)
{
    __shared__ float sh[B_];
    int t = threadIdx.x;
    sh[t] = g_diff[t];
    __syncthreads();
#pragma unroll
    for (int off = B_ / 2; off > 0; off >>= 1) {
        if (t < off) sh[t] += sh[t + off];
        __syncthreads();
    }
    if (t == 0) out[0] = sh[0] / (float)B_;
}

extern "C" void kernel_launch(void* const* d_in, const int* in_sizes, int n_in,
                              void* d_out, int out_size)
{
    const float* emissions = (const float*)d_in[0];
    const int*   tags      = (const int*)d_in[1];
    const float* trans     = (const float*)d_in[2];
    const float* startT    = (const float*)d_in[3];
    const float* endT      = (const float*)d_in[4];
    float* out = (float*)d_out;

    crf_hmma_kernel<<<B_ / SEQ, 128>>>(emissions, tags, trans, startT, endT);
    crf_reduce_kernel<<<1, B_>>>(out);
}

// round 15
// speedup vs baseline: 2.3254x; 2.3254x over previous
#include <cuda_runtime.h>
#include <cuda_bf16.h>
#include <cstdint>

// CRF negative log-likelihood, fixed shapes. sm_100a.
// Scalar recurrence with bf16 state + HFMA2 packed dot (2 MACs/instr).
#define B_ 256
#define S_ 1024
#define T_ 64
#define PF 8   // emission prefetch ring depth; renorm every 4 steps

__device__ float g_diff[B_];

// 128 threads: bat = tid>>6 (2 sequences/block), j = tid&63 (tag).
// grid = 128 (one clean wave). Structure identical to the 152us winner;
// only the alpha storage (bf16) and the dot (HFMA2.BF16) changed.
__global__ void __launch_bounds__(128) crf_forward_kernel(
    const float* __restrict__ emissions,   // (B, S, T)
    const int* __restrict__ tags,          // (B, S) int32
    const float* __restrict__ trans,       // (T, T)
    const float* __restrict__ startT,      // (T,)
    const float* __restrict__ endT)        // (T,)
{
    const int tid = threadIdx.x;
    const int bat = tid >> 6;
    const int j   = tid & 63;
    const int b   = 2 * blockIdx.x + bat;

    __shared__ __align__(16) __nv_bfloat16 u[2][2][T_];   // [buf][bat][tag], 128B/seq
    __shared__ float redA[2][T_];
    __shared__ float redB[2][T_];

    // Packed column of E = exp(trans): epack[m] = (E[2m][j], E[2m+1][j]).
    __nv_bfloat162 epack[T_ / 2];
#pragma unroll
    for (int m = 0; m < T_ / 2; ++m) {
        float lo = __expf(__ldg(trans + (2 * m + 0) * T_ + j));
        float hi = __expf(__ldg(trans + (2 * m + 1) * T_ + j));
        epack[m] = __floats2bfloat162_rn(lo, hi);
    }

    const float* emb = emissions + (size_t)b * S_ * T_ + j;

    // t = 0: u0_j = exp(start_j + em0_j)
    float v = __expf(__ldg(startT + j) + __ldg(emb));
    u[0][bat][j] = __float2bfloat16(v);
    double c = 0.0;   // running log-scale (thread j==0 of each sequence only)

    // Prefetch ring for emissions (raw values, t = 1..PF).
    float pf[PF];
#pragma unroll
    for (int k = 0; k < PF; ++k)
        pf[k] = __ldg(emb + (size_t)(1 + k) * T_);

    __syncthreads();

    int cur = 0;
    int t = 1;

    // Main loop: 127 chunks of 8 steps (t = 1..1016).
#pragma unroll 1
    for (int tb = 0; tb < 127; ++tb) {
#pragma unroll
        for (int k = 0; k < 8; ++k, ++t) {
            float em_t = pf[k];
            if (t + PF < S_)
                pf[k] = __ldg(emb + (size_t)(t + PF) * T_);

            float scale_mul = __expf(em_t);
            if ((k & 3) == 0) {                       // compile-time under unroll
                float scale = __bfloat162float(u[cur][bat][0]);  // broadcast LDS
                if (j == 0) c += (double)__logf(scale);
                scale_mul *= __frcp_rn(scale);
            }

            // 64-MAC dot as 32 HFMA2.BF16: 4 chains (depth 8), 8 LDS.128.
            __nv_bfloat162 z = __floats2bfloat162_rn(0.f, 0.f);
            __nv_bfloat162 a0 = z, a1 = z, a2 = z, a3 = z;
            const uint4* u4 = reinterpret_cast<const uint4*>(u[cur][bat]);
#pragma unroll
            for (int i = 0; i < 8; ++i) {
                uint4 q = u4[i];
                a0 = __hfma2(*(const __nv_bfloat162*)&q.x, epack[4 * i + 0], a0);
                a1 = __hfma2(*(const __nv_bfloat162*)&q.y, epack[4 * i + 1], a1);
                a2 = __hfma2(*(const __nv_bfloat162*)&q.z, epack[4 * i + 2], a2);
                a3 = __hfma2(*(const __nv_bfloat162*)&q.w, epack[4 * i + 3], a3);
            }
            a0 = __hadd2(a0, a1);
            a2 = __hadd2(a2, a3);
            a0 = __hadd2(a0, a2);
            float2 f = __bfloat1622float2(a0);
            v = (f.x + f.y) * scale_mul;

            cur ^= 1;
            u[cur][bat][j] = __float2bfloat16(v);
            __syncthreads();
        }
    }
    // Remainder: t = 1017..1023 (7 steps), emissions already in pf[0..6].
#pragma unroll
    for (int k = 0; k < 7; ++k, ++t) {
        float em_t = pf[k];

        float scale_mul = __expf(em_t);
        if ((k & 3) == 0) {
            float scale = __bfloat162float(u[cur][bat][0]);
            if (j == 0) c += (double)__logf(scale);
            scale_mul *= __frcp_rn(scale);
        }

        __nv_bfloat162 z = __floats2bfloat162_rn(0.f, 0.f);
        __nv_bfloat162 a0 = z, a1 = z, a2 = z, a3 = z;
        const uint4* u4 = reinterpret_cast<const uint4*>(u[cur][bat]);
#pragma unroll
        for (int i = 0; i < 8; ++i) {
            uint4 q = u4[i];
            a0 = __hfma2(*(const __nv_bfloat162*)&q.x, epack[4 * i + 0], a0);
            a1 = __hfma2(*(const __nv_bfloat162*)&q.y, epack[4 * i + 1], a1);
            a2 = __hfma2(*(const __nv_bfloat162*)&q.z, epack[4 * i + 2], a2);
            a3 = __hfma2(*(const __nv_bfloat162*)&q.w, epack[4 * i + 3], a3);
        }
        a0 = __hadd2(a0, a1);
        a2 = __hadd2(a2, a3);
        a0 = __hadd2(a0, a2);
        float2 f = __bfloat1622float2(a0);
        v = (f.x + f.y) * scale_mul;

        cur ^= 1;
        u[cur][bat][j] = __float2bfloat16(v);
        __syncthreads();
    }

    // partition = c + log(sum_j v_j * exp(end_j))   (v held in fp32)
    redA[bat][j] = v * __expf(__ldg(endT + j));

    // Gold-path score, 64 threads per sequence over time steps.
    float sc = 0.f;
    const int* tg = tags + (size_t)b * S_;
    const float* emB = emissions + (size_t)b * S_ * T_;
#pragma unroll 4
    for (int tt = j; tt < S_; tt += T_) {
        int tg0 = tg[tt];
        sc += __ldg(emB + (size_t)tt * T_ + tg0);
        if (tt + 1 < S_) {
            int tg1 = tg[tt + 1];
            sc += __ldg(trans + tg0 * T_ + tg1);
        }
    }
    if (j == 0) {
        sc += __ldg(startT + tg[0]);
        sc += __ldg(endT + tg[S_ - 1]);
    }
    redB[bat][j] = sc;
    __syncthreads();

    if (j == 0) {
        float sumw = 0.f;
        float sums = 0.f;
#pragma unroll
        for (int i = 0; i < T_; ++i) {
            sumw += redA[bat][i];
            sums += redB[bat][i];
        }
        double partition = c + (double)__logf(sumw);
        g_diff[b] = (float)(partition - (double)sums);
    }
}

__global__ void crf_reduce_kernel(float* __restrict__ out)
{
    __shared__ float sh[B_];
    int t = threadIdx.x;
    sh[t] = g_diff[t];
    __syncthreads();
#pragma unroll
    for (int off = B_ / 2; off > 0; off >>= 1) {
        if (t < off) sh[t] += sh[t + off];
        __syncthreads();
    }
    if (t == 0) out[0] = sh[0] / (float)B_;
}

extern "C" void kernel_launch(void* const* d_in, const int* in_sizes, int n_in,
                              void* d_out, int out_size)
{
    const float* emissions = (const float*)d_in[0];
    const int*   tags      = (const int*)d_in[1];
    const float* trans     = (const float*)d_in[2];
    const float* startT    = (const float*)d_in[3];
    const float* endT      = (const float*)d_in[4];
    float* out = (float*)d_out;

    crf_forward_kernel<<<B_ / 2, 128>>>(emissions, tags, trans, startT, endT);
    crf_reduce_kernel<<<1, B_>>>(out);
}